// round 12
// baseline (speedup 1.0000x reference)
#include <cuda_runtime.h>

#define Bx 64
#define Pz 32
#define ATTR 7
#define Cc 224      // A*P*ATTR
#define Rr 4096
#define NLAB 32
#define GRID 1024
#define TPB 256

// accumulators: xy, wl, rot, obj, noobj (zero-init at load; reset by last block each call)
__device__ double g_acc[5];
__device__ unsigned int g_done;

// -max(log(1 - sigmoid(x)), -100) == softplus(x), numerically stable
__device__ __forceinline__ float softplus_fast(float x) {
    return fmaxf(x, 0.0f) + __logf(1.0f + __expf(-fabsf(x)));
}
__device__ __forceinline__ float tanh_approx(float x) {
    float y;
    asm("tanh.approx.f32 %0, %1;" : "=f"(y) : "f"(x));
    return y;
}
__device__ __forceinline__ float sigmoid_fast(float x) {
    return 1.0f / (1.0f + __expf(-x));
}

__global__ void __launch_bounds__(TPB, 6) yolo_fused_kernel(
    const float* __restrict__ preds, const float* __restrict__ labels,
    float* __restrict__ out)
{
    __shared__ int s_key[32];
    __shared__ float red[TPB / 32];

    // ---------- Part 1: object-cell terms (blocks 0..63, warp 0) ----------
    if (blockIdx.x < Bx && threadIdx.x < 32) {
        int b = blockIdx.x, t = threadIdx.x;
        const float* lab = labels + (b * NLAB + t) * ATTR;
        float l0 = lab[0], l1 = lab[1], l2 = lab[2], l3 = lab[3],
              l4 = lab[4], l5 = lab[5];

        float ang = l0 + 204.8f;          // + R*CELL_ANGLE/2
        float q   = ang / 0.1f;           // / CELL_ANGLE
        int i = (int)floorf(q);
        i = min(max(i, 0), Rr - 1);
        float dq = l1;                    // / CELL_DEPTH (=1.0)
        int j = (int)floorf(dq);
        j = min(max(j, 0), Pz - 1);

        int key = i * Pz + j;
        s_key[t] = key;
        __syncwarp();
        bool active = true;               // last-write-wins dedup
        for (int u = t + 1; u < 32; u++)
            if (s_key[u] == key) active = false;

        float sxy = 0.f, swl = 0.f, srot = 0.f, sobj = 0.f, scorr = 0.f;
        if (active) {
            const float* pp = preds + ((size_t)b * Cc + (size_t)j * ATTR) * Rr + i;
            float x0 = pp[0 * Rr], x1 = pp[1 * Rr], x2 = pp[2 * Rr],
                  x3 = pp[3 * Rr], x4 = pp[4 * Rr], x5 = pp[5 * Rr],
                  x6 = pp[6 * Rr];

            float tx = q - (float)i;
            float ty = dq - (float)j;
            float sx = sigmoid_fast(x0);
            float sy = sigmoid_fast(x1);
            sxy = (sx - tx) * (sx - tx) + (sy - ty) * (sy - ty);

            float tw = __logf(l2 * 0.625f + 1e-16f);        // /1.6
            float tl = __logf(l3 * 0.2564102564f + 1e-16f); // /3.9
            swl = (x2 - tw) * (x2 - tw) + (x3 - tl) * (x3 - tl);

            float r0 = tanh_approx(x4), r1 = tanh_approx(x5);
            srot = (r0 - l4) * (r0 - l4) + (r1 - l5) * (r1 - l5);

            // -log(sigmoid(x)) = softplus(-x); log(1-sigmoid(x)) = -softplus(x)
            sobj  = softplus_fast(-x6);
            scorr = -softplus_fast(x6);   // remove this cell from dense noobj sum
        }
        #pragma unroll
        for (int off = 16; off; off >>= 1) {
            sxy   += __shfl_xor_sync(0xffffffffu, sxy,   off);
            swl   += __shfl_xor_sync(0xffffffffu, swl,   off);
            srot  += __shfl_xor_sync(0xffffffffu, srot,  off);
            sobj  += __shfl_xor_sync(0xffffffffu, sobj,  off);
            scorr += __shfl_xor_sync(0xffffffffu, scorr, off);
        }
        if (t == 0) {
            atomicAdd(&g_acc[0], (double)sxy);
            atomicAdd(&g_acc[1], (double)swl);
            atomicAdd(&g_acc[2], (double)srot);
            atomicAdd(&g_acc[3], (double)sobj);
            atomicAdd(&g_acc[4], (double)scorr);
        }
    }

    // ---------- Part 2: dense noobj BCE, row-local mapping ----------
    // R4 structure; launch_bounds(256,6) lifts the reg cap 32 -> 42 so ptxas
    // can keep ~4-5 of the 8 LDG.128 in flight (MLP 2 -> ~4.5) while only
    // dropping 8 -> 6 blocks/SM. Outstanding bytes/SM ~2x -> BW ~2x.
    {
        unsigned tid  = blockIdx.x * TPB + threadIdx.x;
        unsigned gw   = tid >> 5;            // global warp 0..8191
        unsigned lane = tid & 31;
        unsigned row  = gw >> 2;             // 0..2047  (= b*32 + ch)
        unsigned part = gw & 3;
        unsigned b    = row >> 5;
        unsigned ch   = row & 31;
        const float4* p4 = (const float4*)preds;
        const float4* bp = p4 + ((size_t)(b * Cc + ch * ATTR + 6)) * (Rr / 4)
                              + part * 256 + lane;

        float4 d0 = bp[0],   d1 = bp[32],  d2 = bp[64],  d3 = bp[96];
        float4 d4 = bp[128], d5 = bp[160], d6 = bp[192], d7 = bp[224];

        float s0 = softplus_fast(d0.x) + softplus_fast(d0.y)
                 + softplus_fast(d0.z) + softplus_fast(d0.w);
        float s1 = softplus_fast(d1.x) + softplus_fast(d1.y)
                 + softplus_fast(d1.z) + softplus_fast(d1.w);
        float s2 = softplus_fast(d2.x) + softplus_fast(d2.y)
                 + softplus_fast(d2.z) + softplus_fast(d2.w);
        float s3 = softplus_fast(d3.x) + softplus_fast(d3.y)
                 + softplus_fast(d3.z) + softplus_fast(d3.w);
        s0 += softplus_fast(d4.x) + softplus_fast(d4.y)
            + softplus_fast(d4.z) + softplus_fast(d4.w);
        s1 += softplus_fast(d5.x) + softplus_fast(d5.y)
            + softplus_fast(d5.z) + softplus_fast(d5.w);
        s2 += softplus_fast(d6.x) + softplus_fast(d6.y)
            + softplus_fast(d6.z) + softplus_fast(d6.w);
        s3 += softplus_fast(d7.x) + softplus_fast(d7.y)
            + softplus_fast(d7.z) + softplus_fast(d7.w);

        float s = (s0 + s1) + (s2 + s3);
        #pragma unroll
        for (int off = 16; off; off >>= 1)
            s += __shfl_xor_sync(0xffffffffu, s, off);
        int wid = threadIdx.x >> 5, lid = threadIdx.x & 31;
        if (lid == 0) red[wid] = s;
        __syncthreads();
        if (wid == 0) {
            s = (lid < TPB / 32) ? red[lid] : 0.f;
            #pragma unroll
            for (int off = 4; off; off >>= 1)
                s += __shfl_xor_sync(0xffffffffu, s, off);
            if (lid == 0) atomicAdd(&g_acc[4], (double)s);
        }
    }

    // ---------- Part 3: last block finalizes + resets state ----------
    if (threadIdx.x == 0) {
        __threadfence();
        unsigned prev = atomicAdd(&g_done, 1u);
        if (prev == GRID - 1) {
            __threadfence();
            double a0 = *((volatile double*)&g_acc[0]);
            double a1 = *((volatile double*)&g_acc[1]);
            double a2 = *((volatile double*)&g_acc[2]);
            double a3 = *((volatile double*)&g_acc[3]);
            double a4 = *((volatile double*)&g_acc[4]);
            float lxy = (float)a0, lwl = (float)a1, lrot = (float)a2,
                  lobj = (float)a3, lnoobj = (float)a4;
            out[0] = 10.0f * lxy + 10.0f * lwl + 20.0f * lrot +
                     20.0f * lobj + 1.0f * lnoobj;
            out[1] = lxy;
            out[2] = lwl;
            out[3] = lrot;
            out[4] = lobj;
            out[5] = lnoobj;
            g_acc[0] = 0.0; g_acc[1] = 0.0; g_acc[2] = 0.0;
            g_acc[3] = 0.0; g_acc[4] = 0.0;
            g_done = 0u;
            __threadfence();
        }
    }
}

extern "C" void kernel_launch(void* const* d_in, const int* in_sizes, int n_in,
                              void* d_out, int out_size) {
    const float* preds  = (const float*)d_in[0];
    const float* labels = (const float*)d_in[1];
    float* out = (float*)d_out;

    yolo_fused_kernel<<<GRID, TPB>>>(preds, labels, out);
}

// round 13
// speedup vs baseline: 1.4419x; 1.4419x over previous
#include <cuda_runtime.h>

#define Bx 64
#define Pz 32
#define ATTR 7
#define Cc 224      // A*P*ATTR
#define Rr 4096
#define NLAB 32
#define GRID 1024
#define TPB 256
#define CHUNK_BYTES 8192           // 8KB chunk = half a conf row
#define CHUNK_F4 (CHUNK_BYTES/16)  // 512 float4
#define NCHUNK 4                   // 2 rows per block
#define NSTAGE 3                   // smem ring

// accumulators: xy, wl, rot, obj, noobj (zero-init at load; reset by last block each call)
__device__ double g_acc[5];
__device__ unsigned int g_done;

__device__ __forceinline__ float softplus_fast(float x) {
    return fmaxf(x, 0.0f) + __logf(1.0f + __expf(-fabsf(x)));
}
__device__ __forceinline__ float tanh_approx(float x) {
    float y;
    asm("tanh.approx.f32 %0, %1;" : "=f"(y) : "f"(x));
    return y;
}
__device__ __forceinline__ float sigmoid_fast(float x) {
    return 1.0f / (1.0f + __expf(-x));
}
__device__ __forceinline__ unsigned smem_u32(const void* p) {
    return (unsigned)__cvta_generic_to_shared(p);
}
__device__ __forceinline__ void mbar_wait(unsigned bar, unsigned phase) {
    unsigned done;
    asm volatile(
        "{\n\t.reg .pred p;\n\t"
        "mbarrier.try_wait.parity.acquire.cta.shared::cta.b64 p, [%1], %2;\n\t"
        "selp.b32 %0, 1, 0, p;\n\t}"
        : "=r"(done) : "r"(bar), "r"(phase) : "memory");
    if (!done) {
        asm volatile(
            "{\n\t.reg .pred P1;\n\t"
            "WL_%=:\n\t"
            "mbarrier.try_wait.parity.acquire.cta.shared::cta.b64 P1, [%0], %1, 0x989680;\n\t"
            "@P1 bra.uni WD_%=;\n\t"
            "bra.uni WL_%=;\n\t"
            "WD_%=:\n\t}"
            :: "r"(bar), "r"(phase) : "memory");
    }
}
__device__ __forceinline__ void tma_issue(unsigned dst, const char* src, unsigned bar) {
    asm volatile("mbarrier.arrive.expect_tx.shared.b64 _, [%0], %1;"
                 :: "r"(bar), "r"((unsigned)CHUNK_BYTES) : "memory");
    asm volatile(
        "cp.async.bulk.shared::cluster.global.mbarrier::complete_tx::bytes "
        "[%0], [%1], %2, [%3];"
        :: "r"(dst), "l"(src), "r"((unsigned)CHUNK_BYTES), "r"(bar) : "memory");
}

__global__ void __launch_bounds__(TPB) yolo_fused_kernel(
    const float* __restrict__ preds, const float* __restrict__ labels,
    float* __restrict__ out)
{
    __shared__ __align__(128) float4 buf[NSTAGE][CHUNK_F4];   // 3 x 8KB
    __shared__ __align__(8) unsigned long long mbar[NSTAGE];
    __shared__ int s_key[32];
    __shared__ float red[TPB / 32];

    const int tid = threadIdx.x;

    // chunk c (0..3): row = blockIdx*2 + (c>>1), byte offset (c&1)*8KB
    // row r -> image r>>5, depth ch r&31; conf row base = ((r>>5)*Cc + (r&31)*ATTR + 6)*16KB
    if (tid == 0) {
        #pragma unroll
        for (int i = 0; i < NSTAGE; i++)
            asm volatile("mbarrier.init.shared.b64 [%0], 1;"
                         :: "r"(smem_u32(&mbar[i])) : "memory");
    }
    __syncthreads();

    if (tid == 0) {
        #pragma unroll
        for (int c = 0; c < NSTAGE; c++) {       // issue chunks 0,1,2 up-front
            int row = blockIdx.x * 2 + (c >> 1);
            const char* src = (const char*)preds
                + ((size_t)((row >> 5) * Cc + (row & 31) * ATTR + 6)) * 16384
                + (c & 1) * CHUNK_BYTES;
            tma_issue(smem_u32(&buf[c][0]), src, smem_u32(&mbar[c]));
        }
    }

    // ---------- Part 1: object-cell terms, overlapped with TMA latency ----------
    if (blockIdx.x < Bx && tid < 32) {
        int bb = blockIdx.x, t = tid;
        const float* lab = labels + (bb * NLAB + t) * ATTR;
        float l0 = lab[0], l1 = lab[1], l2 = lab[2], l3 = lab[3],
              l4 = lab[4], l5 = lab[5];

        float ang = l0 + 204.8f;
        float q   = ang / 0.1f;
        int i = (int)floorf(q);
        i = min(max(i, 0), Rr - 1);
        float dq = l1;
        int j = (int)floorf(dq);
        j = min(max(j, 0), Pz - 1);

        int key = i * Pz + j;
        s_key[t] = key;
        __syncwarp();
        bool active = true;               // last-write-wins dedup
        for (int u = t + 1; u < 32; u++)
            if (s_key[u] == key) active = false;

        float sxy = 0.f, swl = 0.f, srot = 0.f, sobj = 0.f, scorr = 0.f;
        if (active) {
            const float* pp = preds + ((size_t)bb * Cc + (size_t)j * ATTR) * Rr + i;
            float x0 = pp[0 * Rr], x1 = pp[1 * Rr], x2 = pp[2 * Rr],
                  x3 = pp[3 * Rr], x4 = pp[4 * Rr], x5 = pp[5 * Rr],
                  x6 = pp[6 * Rr];

            float tx = q - (float)i;
            float ty = dq - (float)j;
            float sx = sigmoid_fast(x0);
            float sy = sigmoid_fast(x1);
            sxy = (sx - tx) * (sx - tx) + (sy - ty) * (sy - ty);

            float tw = __logf(l2 * 0.625f + 1e-16f);
            float tl = __logf(l3 * 0.2564102564f + 1e-16f);
            swl = (x2 - tw) * (x2 - tw) + (x3 - tl) * (x3 - tl);

            float r0 = tanh_approx(x4), r1 = tanh_approx(x5);
            srot = (r0 - l4) * (r0 - l4) + (r1 - l5) * (r1 - l5);

            sobj  = softplus_fast(-x6);
            scorr = -softplus_fast(x6);
        }
        #pragma unroll
        for (int off = 16; off; off >>= 1) {
            sxy   += __shfl_xor_sync(0xffffffffu, sxy,   off);
            swl   += __shfl_xor_sync(0xffffffffu, swl,   off);
            srot  += __shfl_xor_sync(0xffffffffu, srot,  off);
            sobj  += __shfl_xor_sync(0xffffffffu, sobj,  off);
            scorr += __shfl_xor_sync(0xffffffffu, scorr, off);
        }
        if (t == 0) {
            atomicAdd(&g_acc[0], (double)sxy);
            atomicAdd(&g_acc[1], (double)swl);
            atomicAdd(&g_acc[2], (double)srot);
            atomicAdd(&g_acc[3], (double)sobj);
            atomicAdd(&g_acc[4], (double)scorr);
        }
    }

    // ---------- Part 2: consume 4 chunks through the 3-stage ring ----------
    float acc0 = 0.f, acc1 = 0.f;

    // chunk 0 (stage 0, phase 0)
    mbar_wait(smem_u32(&mbar[0]), 0);
    {
        float4 d0 = buf[0][tid];
        float4 d1 = buf[0][tid + 256];
        acc0 += softplus_fast(d0.x) + softplus_fast(d0.y)
              + softplus_fast(d0.z) + softplus_fast(d0.w);
        acc1 += softplus_fast(d1.x) + softplus_fast(d1.y)
              + softplus_fast(d1.z) + softplus_fast(d1.w);
    }
    __syncthreads();                      // everyone done reading stage 0
    if (tid == 0) {                       // refill: chunk 3 -> stage 0
        asm volatile("fence.proxy.async.shared::cta;" ::: "memory");
        int row = blockIdx.x * 2 + 1;
        const char* src = (const char*)preds
            + ((size_t)((row >> 5) * Cc + (row & 31) * ATTR + 6)) * 16384
            + CHUNK_BYTES;
        tma_issue(smem_u32(&buf[0][0]), src, smem_u32(&mbar[0]));
    }

    // chunks 1, 2 (stages 1, 2, phase 0)
    #pragma unroll
    for (int c = 1; c < 3; c++) {
        mbar_wait(smem_u32(&mbar[c]), 0);
        float4 d0 = buf[c][tid];
        float4 d1 = buf[c][tid + 256];
        acc0 += softplus_fast(d0.x) + softplus_fast(d0.y)
              + softplus_fast(d0.z) + softplus_fast(d0.w);
        acc1 += softplus_fast(d1.x) + softplus_fast(d1.y)
              + softplus_fast(d1.z) + softplus_fast(d1.w);
    }

    // chunk 3 (stage 0, phase 1)
    mbar_wait(smem_u32(&mbar[0]), 1);
    {
        float4 d0 = buf[0][tid];
        float4 d1 = buf[0][tid + 256];
        acc0 += softplus_fast(d0.x) + softplus_fast(d0.y)
              + softplus_fast(d0.z) + softplus_fast(d0.w);
        acc1 += softplus_fast(d1.x) + softplus_fast(d1.y)
              + softplus_fast(d1.z) + softplus_fast(d1.w);
    }

    float s = acc0 + acc1;
    #pragma unroll
    for (int off = 16; off; off >>= 1)
        s += __shfl_xor_sync(0xffffffffu, s, off);
    int wid = tid >> 5, lid = tid & 31;
    if (lid == 0) red[wid] = s;
    __syncthreads();
    if (wid == 0) {
        s = (lid < TPB / 32) ? red[lid] : 0.f;
        #pragma unroll
        for (int off = 4; off; off >>= 1)
            s += __shfl_xor_sync(0xffffffffu, s, off);
        if (lid == 0) atomicAdd(&g_acc[4], (double)s);
    }

    // ---------- Part 3: last block finalizes + resets state ----------
    if (tid == 0) {
        __threadfence();
        unsigned prev = atomicAdd(&g_done, 1u);
        if (prev == GRID - 1) {
            __threadfence();
            double a0 = *((volatile double*)&g_acc[0]);
            double a1 = *((volatile double*)&g_acc[1]);
            double a2 = *((volatile double*)&g_acc[2]);
            double a3 = *((volatile double*)&g_acc[3]);
            double a4 = *((volatile double*)&g_acc[4]);
            float lxy = (float)a0, lwl = (float)a1, lrot = (float)a2,
                  lobj = (float)a3, lnoobj = (float)a4;
            out[0] = 10.0f * lxy + 10.0f * lwl + 20.0f * lrot +
                     20.0f * lobj + 1.0f * lnoobj;
            out[1] = lxy;
            out[2] = lwl;
            out[3] = lrot;
            out[4] = lobj;
            out[5] = lnoobj;
            g_acc[0] = 0.0; g_acc[1] = 0.0; g_acc[2] = 0.0;
            g_acc[3] = 0.0; g_acc[4] = 0.0;
            g_done = 0u;
            __threadfence();
        }
    }
}

extern "C" void kernel_launch(void* const* d_in, const int* in_sizes, int n_in,
                              void* d_out, int out_size) {
    const float* preds  = (const float*)d_in[0];
    const float* labels = (const float*)d_in[1];
    float* out = (float*)d_out;

    yolo_fused_kernel<<<GRID, TPB>>>(preds, labels, out);
}

// round 14
// speedup vs baseline: 1.6994x; 1.1786x over previous
#include <cuda_runtime.h>

#define Bx 64
#define Pz 32
#define ATTR 7
#define Cc 224      // A*P*ATTR
#define Rr 4096
#define NLAB 32
#define GRID 1024
#define TPB 256

// accumulators: xy, wl, rot, obj, noobj (zero-init at load; reset by last block each call)
__device__ double g_acc[5];
__device__ unsigned int g_done;

__device__ __forceinline__ float softplus_fast(float x) {
    return fmaxf(x, 0.0f) + __logf(1.0f + __expf(-fabsf(x)));
}
__device__ __forceinline__ float tanh_approx(float x) {
    float y;
    asm("tanh.approx.f32 %0, %1;" : "=f"(y) : "f"(x));
    return y;
}
__device__ __forceinline__ float sigmoid_fast(float x) {
    return 1.0f / (1.0f + __expf(-x));
}

__global__ void __launch_bounds__(TPB) yolo_fused_kernel(
    const float* __restrict__ preds, const float* __restrict__ labels,
    float* __restrict__ out)
{
    __shared__ float4 ring[4][TPB];     // 16KB: 4-slot per-thread staging ring
    __shared__ int s_key[32];
    __shared__ float red[TPB / 32];

    const int tid = threadIdx.x;

    // ---------- dense mapping (R4 row-local): warp streams 4KB span ----------
    unsigned gt   = blockIdx.x * TPB + tid;
    unsigned gw   = gt >> 5;
    unsigned lane = gt & 31;
    unsigned row  = gw >> 2;             // b*32 + ch
    unsigned part = gw & 3;
    unsigned b    = row >> 5;
    unsigned ch   = row & 31;
    const float4* p4 = (const float4*)preds;
    const float4* bp = p4 + ((size_t)(b * Cc + ch * ATTR + 6)) * (Rr / 4)
                          + part * 256 + lane;

    // ---------- prologue: fill the ring (chunks 0..3), one commit group each ----------
    #define ISSUE(k, slot)                                                    \
    {                                                                         \
        unsigned sa = (unsigned)__cvta_generic_to_shared(&ring[slot][tid]);   \
        asm volatile("cp.async.cg.shared.global [%0], [%1], 16;\n\t"          \
                     "cp.async.commit_group;"                                 \
                     :: "r"(sa), "l"(bp + (k) * 32) : "memory");              \
    }
    ISSUE(0, 0) ISSUE(1, 1) ISSUE(2, 2) ISSUE(3, 3)

    // ---------- Part 1: object-cell terms, overlapped with first loads ----------
    if (blockIdx.x < Bx && tid < 32) {
        int bb = blockIdx.x, t = tid;
        const float* lab = labels + (bb * NLAB + t) * ATTR;
        float l0 = lab[0], l1 = lab[1], l2 = lab[2], l3 = lab[3],
              l4 = lab[4], l5 = lab[5];

        float ang = l0 + 204.8f;
        float q   = ang / 0.1f;
        int i = (int)floorf(q);
        i = min(max(i, 0), Rr - 1);
        float dq = l1;
        int j = (int)floorf(dq);
        j = min(max(j, 0), Pz - 1);

        int key = i * Pz + j;
        s_key[t] = key;
        __syncwarp();
        bool active = true;               // last-write-wins dedup
        for (int u = t + 1; u < 32; u++)
            if (s_key[u] == key) active = false;

        float sxy = 0.f, swl = 0.f, srot = 0.f, sobj = 0.f, scorr = 0.f;
        if (active) {
            const float* pp = preds + ((size_t)bb * Cc + (size_t)j * ATTR) * Rr + i;
            float x0 = pp[0 * Rr], x1 = pp[1 * Rr], x2 = pp[2 * Rr],
                  x3 = pp[3 * Rr], x4 = pp[4 * Rr], x5 = pp[5 * Rr],
                  x6 = pp[6 * Rr];

            float tx = q - (float)i;
            float ty = dq - (float)j;
            float sx = sigmoid_fast(x0);
            float sy = sigmoid_fast(x1);
            sxy = (sx - tx) * (sx - tx) + (sy - ty) * (sy - ty);

            float tw = __logf(l2 * 0.625f + 1e-16f);
            float tl = __logf(l3 * 0.2564102564f + 1e-16f);
            swl = (x2 - tw) * (x2 - tw) + (x3 - tl) * (x3 - tl);

            float r0 = tanh_approx(x4), r1 = tanh_approx(x5);
            srot = (r0 - l4) * (r0 - l4) + (r1 - l5) * (r1 - l5);

            sobj  = softplus_fast(-x6);
            scorr = -softplus_fast(x6);
        }
        #pragma unroll
        for (int off = 16; off; off >>= 1) {
            sxy   += __shfl_xor_sync(0xffffffffu, sxy,   off);
            swl   += __shfl_xor_sync(0xffffffffu, swl,   off);
            srot  += __shfl_xor_sync(0xffffffffu, srot,  off);
            sobj  += __shfl_xor_sync(0xffffffffu, sobj,  off);
            scorr += __shfl_xor_sync(0xffffffffu, scorr, off);
        }
        if (t == 0) {
            atomicAdd(&g_acc[0], (double)sxy);
            atomicAdd(&g_acc[1], (double)swl);
            atomicAdd(&g_acc[2], (double)srot);
            atomicAdd(&g_acc[3], (double)sobj);
            atomicAdd(&g_acc[4], (double)scorr);
        }
    }

    // ---------- Part 2: pipelined consume — compute chunk k while k+1..k+3 fly ----------
    float sA = 0.f, sB = 0.f;

    #define CONSUME(slot, accv)                                               \
    {                                                                         \
        float4 d = ring[slot][tid];                                           \
        accv += (softplus_fast(d.x) + softplus_fast(d.y))                     \
              + (softplus_fast(d.z) + softplus_fast(d.w));                    \
    }
    #define WAITG(n) asm volatile("cp.async.wait_group %0;" :: "n"(n) : "memory");

    WAITG(3) CONSUME(0, sA) ISSUE(4, 0)     // pending: 1,2,3,4
    WAITG(3) CONSUME(1, sB) ISSUE(5, 1)     // pending: 2,3,4,5
    WAITG(3) CONSUME(2, sA) ISSUE(6, 2)     // pending: 3,4,5,6
    WAITG(3) CONSUME(3, sB) ISSUE(7, 3)     // pending: 4,5,6,7
    WAITG(3) CONSUME(0, sA)                 // chunk 4 ready
    WAITG(2) CONSUME(1, sB)                 // chunk 5
    WAITG(1) CONSUME(2, sA)                 // chunk 6
    WAITG(0) CONSUME(3, sB)                 // chunk 7
    #undef WAITG
    #undef CONSUME
    #undef ISSUE

    float s = sA + sB;
    #pragma unroll
    for (int off = 16; off; off >>= 1)
        s += __shfl_xor_sync(0xffffffffu, s, off);
    int wid = tid >> 5, lid = tid & 31;
    if (lid == 0) red[wid] = s;
    __syncthreads();
    if (wid == 0) {
        s = (lid < TPB / 32) ? red[lid] : 0.f;
        #pragma unroll
        for (int off = 4; off; off >>= 1)
            s += __shfl_xor_sync(0xffffffffu, s, off);
        if (lid == 0) atomicAdd(&g_acc[4], (double)s);
    }

    // ---------- Part 3: last block finalizes + resets state ----------
    if (tid == 0) {
        __threadfence();
        unsigned prev = atomicAdd(&g_done, 1u);
        if (prev == GRID - 1) {
            __threadfence();
            double a0 = *((volatile double*)&g_acc[0]);
            double a1 = *((volatile double*)&g_acc[1]);
            double a2 = *((volatile double*)&g_acc[2]);
            double a3 = *((volatile double*)&g_acc[3]);
            double a4 = *((volatile double*)&g_acc[4]);
            float lxy = (float)a0, lwl = (float)a1, lrot = (float)a2,
                  lobj = (float)a3, lnoobj = (float)a4;
            out[0] = 10.0f * lxy + 10.0f * lwl + 20.0f * lrot +
                     20.0f * lobj + 1.0f * lnoobj;
            out[1] = lxy;
            out[2] = lwl;
            out[3] = lrot;
            out[4] = lobj;
            out[5] = lnoobj;
            g_acc[0] = 0.0; g_acc[1] = 0.0; g_acc[2] = 0.0;
            g_acc[3] = 0.0; g_acc[4] = 0.0;
            g_done = 0u;
            __threadfence();
        }
    }
}

extern "C" void kernel_launch(void* const* d_in, const int* in_sizes, int n_in,
                              void* d_out, int out_size) {
    const float* preds  = (const float*)d_in[0];
    const float* labels = (const float*)d_in[1];
    float* out = (float*)d_out;

    yolo_fused_kernel<<<GRID, TPB>>>(preds, labels, out);
}